// round 7
// baseline (speedup 1.0000x reference)
#include <cuda_runtime.h>
#include <math.h>

#define DIM 4096
#define NDIAG_BLK 32          // blocks that also compute the fp64 diagonal
#define FILL_BLOCKS 16384     // 16384 * 256 threads * 16 B = 64 MiB exactly

// First 30 primes (== P_DIAG == P_OFF for DIM=4096).
__constant__ int c_primes[30] = {
    2, 3, 5, 7, 11, 13, 17, 19, 23, 29,
    31, 37, 41, 43, 47, 53, 59, 61, 67, 71,
    73, 79, 83, 89, 97, 101, 103, 107, 109, 113};

// Scratch (__device__ globals: allocation-free, zero-initialized at load).
__device__ double g_diag[DIM];
__device__ double g_partial[NDIAG_BLK];
__device__ double g_reg;
__device__ unsigned int g_arrive;   // diag blocks finished
__device__ unsigned int g_ready;    // release flag: g_diag/g_reg published
__device__ unsigned int g_done;     // splicers finished (drives state reset)

// ---------------------------------------------------------------------------
// Single fused kernel.
//  * Blocks 0..31 (wave-1 resident by launch order): compute the fp64
//    diagonal d[n] = Re(exp(-s ln n)) + prime correction, block-reduce
//    sum-of-squares, last arriver folds partials -> g_reg, sets g_ready.
//  * ALL blocks: write one float4 of zeros per thread (the 64 MiB fill —
//    independent of the diagonal, streams immediately).
//  * The 4096 threads whose float4 contains a diagonal element spin on
//    g_ready, then splice d[row]+reg. Last splicer resets the flags so the
//    kernel is replay-deterministic under CUDA graphs.
// Off-diagonal prime terms are purely imaginary and cancel EXACTLY under
// Hermitization, so Re(H) is diagonal; reg = max(1e-22, ||diag|| * 1e-18).
// ---------------------------------------------------------------------------
__global__ __launch_bounds__(256)
void fused_kernel(const float* sr_p, const float* si_p, const float* th_p,
                  float4* __restrict__ out) {
    const unsigned int bid = blockIdx.x;
    const unsigned int tid = threadIdx.x;

    // ---------------- Phase A: diagonal compute (blocks 0..31) -------------
    if (bid < NDIAG_BLK) {
        __shared__ double warp_s[4];
        if (tid < 128) {
            const double ZETA2 = 1.6449340668482264365;  // pi^2/6
            const double CUTOFF = 1e-80;
            const double sr = sr_p ? (double)*sr_p : 0.5;
            const double si = si_p ? (double)*si_p : 14.134725141734693;
            const double th = th_p ? (double)*th_p : 1e-22;

            const bool in_range = (fabs(sr) < 30.0) && (fabs(si) < 500.0);
            const double corr = fmin(sqrt(sr * sr + si * si), 5.0);

            const int t = (int)(bid * 128u + tid);  // 0..4095
            const int n = t + 1;                    // 1..4096
            const double logn = log((double)n);
            const bool safe = (-sr * logn) > -80.0;
            double re = (in_range || safe) ? exp(-sr * logn) * cos(si * logn)
                                           : CUTOFF;
            if (n <= 113) {
                bool isp = false;
#pragma unroll
                for (int j = 0; j < 30; j++) isp = isp || (n == c_primes[j]);
                if (isp) re += th * logn * corr * (ZETA2 / (double)n);
            }
            g_diag[t] = re;

            double ss = re * re;
#pragma unroll
            for (int o = 16; o > 0; o >>= 1)
                ss += __shfl_down_sync(0xffffffffu, ss, o);
            if ((tid & 31u) == 0) warp_s[tid >> 5] = ss;
        }
        __syncthreads();
        if (tid == 0) {
            g_partial[bid] = warp_s[0] + warp_s[1] + warp_s[2] + warp_s[3];
            __threadfence();
            const unsigned int old = atomicAdd(&g_arrive, 1u);
            if (old == NDIAG_BLK - 1) {
                // Deterministic ordered fold of the 32 partials.
                double s = 0.0;
#pragma unroll
                for (int i = 0; i < NDIAG_BLK; i++)
                    s += ((volatile double*)g_partial)[i];
                g_reg = fmax(1e-22, sqrt(s) * 1e-18);
                __threadfence();          // release g_diag + g_reg
                *((volatile unsigned int*)&g_ready) = 1u;
            }
        }
    }

    // ---------------- Phase B: 64 MiB zero fill + diagonal splice ----------
    const unsigned int idx = bid * 256u + tid;   // 0..4,194,303 float4 slots
    const unsigned int row = idx >> 10;          // 1024 float4 per row
    const unsigned int col4 = idx & 1023u;

    if (col4 != (row >> 2)) {
        out[idx] = make_float4(0.f, 0.f, 0.f, 0.f);
    } else {
        // This float4 holds diagonal element (row, row). Wait for g_reg.
        volatile unsigned int* ready = &g_ready;
        while (*ready == 0u) __nanosleep(64);
        __threadfence();                 // acquire g_diag / g_reg

        float4 v = make_float4(0.f, 0.f, 0.f, 0.f);
        const double d = ((volatile double*)g_diag)[row] +
                         *((volatile double*)&g_reg);
        const float df = (float)d;
        switch (row & 3u) {
            case 0:  v.x = df; break;
            case 1:  v.y = df; break;
            case 2:  v.z = df; break;
            default: v.w = df; break;
        }
        out[idx] = v;

        // Last splicer resets the cross-replay state (graph-replay safe).
        const unsigned int o = atomicAdd(&g_done, 1u);
        if (o == DIM - 1) {
            g_arrive = 0u;
            g_done = 0u;
            *((volatile unsigned int*)&g_ready) = 0u;
            __threadfence();
        }
    }
}

extern "C" void kernel_launch(void* const* d_in, const int* in_sizes, int n_in,
                              void* d_out, int out_size) {
    (void)in_sizes; (void)out_size;
    const float* sr = (n_in >= 1) ? (const float*)d_in[0] : 0;
    const float* si = (n_in >= 2) ? (const float*)d_in[1] : 0;
    const float* th = (n_in >= 3) ? (const float*)d_in[2] : 0;

    fused_kernel<<<FILL_BLOCKS, 256>>>(sr, si, th, (float4*)d_out);
}